// round 14
// baseline (speedup 1.0000x reference)
#include <cuda_runtime.h>
#include <cuda_fp16.h>
#include <cstdint>

// CoherenceGate via fp16 mma.sync.m16n8k16 (sm_100 baseline ISA).
// out = sigmoid( psi_re*(psi_re@W^T) + psi_im*(psi_im@W^T) + bias )
// B=8192, K=1024.
//
// R14: R13 GEMM (fp16-psi epilogue, folded W_INV — 106.2us measured) with the
//      psi fp32->fp16 conversion folded in via a deadlock-free HELP-FIRST
//      protocol: 512 band-ordered chunks, any CTA needing an unready band
//      converts chunks itself until the band's 4-chunk arrival count is met.
//      Tiny pre-kernel converts W and resets counters/flags.

#define KDIM 1024
#define BDIM 8192
#define BM 64
#define BN 128
#define BK 64
#define NTHREADS 256
#define PIPE 3
#define NS (KDIM / BK)      // 16
#define NBANDS (BDIM / BM)  // 128
#define NTILES (NBANDS * (KDIM / BN))   // 1024
#define GRID_PERSIST 296

#define NCHUNK (NBANDS * 4)   // 512 convert chunks (16 rows re+im each)

#define W_SCALE 256.0f
#define W_INV   (1.0f / 256.0f)

#define OFF_ARE 0
#define OFF_AIM 8192
#define OFF_W   16384
#define STAGE_BYTES 32768
#define SMEM_BYTES (PIPE * STAGE_BYTES)   // 98304 per CTA

__device__ __half g_pre16[(size_t)BDIM * KDIM];
__device__ __half g_pim16[(size_t)BDIM * KDIM];
__device__ __half g_W16[(size_t)KDIM * KDIM];
__device__ unsigned g_tile_ctr;
__device__ unsigned g_cvt_ctr;
__device__ unsigned g_band_cnt[NBANDS];

__device__ __forceinline__ uint32_t smem_u32(const void* p) {
    uint32_t a;
    asm("{ .reg .u64 t; cvta.to.shared.u64 t, %1; cvt.u32.u64 %0, t; }" : "=r"(a) : "l"(p));
    return a;
}
__device__ __forceinline__ void cp16(uint32_t dst, const void* src) {
    asm volatile("cp.async.cg.shared.global [%0], [%1], 16;" :: "r"(dst), "l"(src) : "memory");
}
__device__ __forceinline__ void ldsm4(uint32_t* r, uint32_t addr) {
    asm volatile("ldmatrix.sync.aligned.m8n8.x4.shared.b16 {%0,%1,%2,%3}, [%4];"
                 : "=r"(r[0]), "=r"(r[1]), "=r"(r[2]), "=r"(r[3]) : "r"(addr));
}
__device__ __forceinline__ void mma16(float* d, const uint32_t* a, const uint32_t* b) {
    asm volatile(
        "mma.sync.aligned.m16n8k16.row.col.f32.f16.f16.f32 "
        "{%0,%1,%2,%3},{%4,%5,%6,%7},{%8,%9},{%0,%1,%2,%3};"
        : "+f"(d[0]), "+f"(d[1]), "+f"(d[2]), "+f"(d[3])
        : "r"(a[0]), "r"(a[1]), "r"(a[2]), "r"(a[3]), "r"(b[0]), "r"(b[1]));
}
__device__ __forceinline__ float sigf(float x) {
    float t;
    asm("tanh.approx.f32 %0, %1;" : "=f"(t) : "f"(0.5f * x));
    return fmaf(0.5f, t, 0.5f);
}

// ---------------- pre-kernel: W convert + state reset ----------------
__global__ void reset_cvtW_kernel(const float4* __restrict__ Wm)
{
    const int gid = blockIdx.x * blockDim.x + threadIdx.x;
    const int stride = gridDim.x * blockDim.x;
    if (gid == 0) { g_tile_ctr = 0u; g_cvt_ctr = 0u; }
    if (gid < NBANDS) g_band_cnt[gid] = 0u;

    uint2* dst = reinterpret_cast<uint2*>(g_W16);
    const int n4 = (KDIM * KDIM) / 4;
    for (int i = gid; i < n4; i += stride) {
        const float4 v = Wm[i];
        const __half2 h0 = __floats2half2_rn(v.x * W_SCALE, v.y * W_SCALE);
        const __half2 h1 = __floats2half2_rn(v.z * W_SCALE, v.w * W_SCALE);
        uint2 o;
        o.x = *(const uint32_t*)&h0;
        o.y = *(const uint32_t*)&h1;
        dst[i] = o;
    }
}

// ---------------- psi chunk conversion (help-first) ----------------
// chunk c: band b = c>>2, part j = c&3 -> rows [b*64+j*16, +16), re+im.
__device__ void convert_chunk(const float4* __restrict__ pre4,
                              const float4* __restrict__ pim4,
                              int c, int tid)
{
    const int base4 = ((c >> 2) * 64 + (c & 3) * 16) * 256;   // float4 index (256 f4/row)
    uint2* dr = reinterpret_cast<uint2*>(g_pre16) + base4;
    uint2* di = reinterpret_cast<uint2*>(g_pim16) + base4;
    const float4* pr = pre4 + base4;
    const float4* pi = pim4 + base4;
#pragma unroll 4
    for (int i = 0; i < 16; ++i) {
        const int idx = tid + i * 256;
        const float4 a = pr[idx];
        const float4 b = pi[idx];
        const __half2 a0 = __floats2half2_rn(a.x, a.y);
        const __half2 a1 = __floats2half2_rn(a.z, a.w);
        const __half2 b0 = __floats2half2_rn(b.x, b.y);
        const __half2 b1 = __floats2half2_rn(b.z, b.w);
        uint2 oa, ob;
        oa.x = *(const uint32_t*)&a0;  oa.y = *(const uint32_t*)&a1;
        ob.x = *(const uint32_t*)&b0;  ob.y = *(const uint32_t*)&b1;
        dr[idx] = oa;
        di[idx] = ob;
    }
}

// Deadlock-free: each iteration either the band is ready (exit), we convert a
// chunk (global progress), or all chunks are claimed by CTAs that never wait.
__device__ void ensure_band(const float4* __restrict__ pre4,
                            const float4* __restrict__ pim4,
                            int band, int tid, volatile unsigned* s_cvt)
{
    for (;;) {
        if (tid == 0) {
            if (*(volatile unsigned*)&g_band_cnt[band] >= 4u)
                *s_cvt = 0xFFFFFFFFu;
            else
                *s_cvt = atomicAdd(&g_cvt_ctr, 1u);
        }
        __syncthreads();
        const unsigned c = *s_cvt;
        __syncthreads();
        if (c == 0xFFFFFFFFu) break;
        if (c < NCHUNK) {
            convert_chunk(pre4, pim4, (int)c, tid);
            __threadfence();
            __syncthreads();
            if (tid == 0) atomicAdd(&g_band_cnt[c >> 2], 1u);
        } else {
            __nanosleep(100);
        }
    }
    __threadfence();   // acquire converted data before cp.async reads it
}

// ---------------- stage loader (8 cp.async / thread) ----------------
__device__ __forceinline__ void load_stage(uint32_t sbase, int buf, int j0,
                                           int block_b, int block_k, int tid)
{
    const uint32_t sb = sbase + (uint32_t)buf * STAGE_BYTES;
#pragma unroll
    for (int t = 0; t < 2; ++t) {
        const int idx = tid + t * 256;
        const int row = idx >> 3;
        const int ch  = idx & 7;
        const uint32_t so = (uint32_t)(row * 128 + ((ch ^ (row & 7)) * 16));
        const size_t ga = (size_t)(block_b + row) * KDIM + j0 + ch * 8;
        cp16(sb + OFF_ARE + so, g_pre16 + ga);
        cp16(sb + OFF_AIM + so, g_pim16 + ga);
    }
#pragma unroll
    for (int t = 0; t < 4; ++t) {
        const int idx = tid + t * 256;
        const int row = idx >> 3;
        const int ch  = idx & 7;
        const uint32_t so = (uint32_t)(row * 128 + ((ch ^ (row & 7)) * 16));
        cp16(sb + OFF_W + so, g_W16 + (size_t)(block_k + row) * KDIM + j0 + ch * 8);
    }
}

__device__ __forceinline__ void prologue_tile(uint32_t sbase, int block_b, int block_k, int tid)
{
    load_stage(sbase, 0, 0, block_b, block_k, tid);
    asm volatile("cp.async.commit_group;" ::: "memory");
    load_stage(sbase, 1, BK, block_b, block_k, tid);
    asm volatile("cp.async.commit_group;" ::: "memory");
}

// ---------------- persistent dual-GEMM + fused sigmoid ----------------
__global__ __launch_bounds__(NTHREADS, 2)
void coherence_gate_h(const float* __restrict__ pre,
                      const float* __restrict__ pim,
                      const float* __restrict__ bias,
                      float* __restrict__ out)
{
    extern __shared__ __align__(128) char smem[];
    const uint32_t sbase = smem_u32(smem);
    __shared__ unsigned s_next;
    __shared__ unsigned s_cvt;

    const float4* pre4 = reinterpret_cast<const float4*>(pre);
    const float4* pim4 = reinterpret_cast<const float4*>(pim);

    const int tid    = threadIdx.x;
    const int wid    = tid >> 5;
    const int lane   = tid & 31;
    const int g      = lane >> 2;
    const int tg     = lane & 3;
    const int warp_m = wid >> 2;   // 0..1 -> 32-row band
    const int warp_n = wid & 3;    // 0..3 -> 32-col band

    const int a_rl  = lane & 15;
    const int a_chi = lane >> 4;
    const int w_M   = lane >> 3;
    const int w_r   = lane & 7;
    const int w_kc  = w_M & 1;
    const int w_nadd = (w_M >> 1) * 8;

    int abase[2], axor[2];
#pragma unroll
    for (int mt = 0; mt < 2; ++mt) {
        const int arow = warp_m * 32 + mt * 16 + a_rl;
        abase[mt] = arow * 128;
        axor[mt]  = arow & 7;
    }
    int wbase[2], wxor[2];
#pragma unroll
    for (int ntp = 0; ntp < 2; ++ntp) {
        const int wrow = warp_n * 32 + ntp * 16 + w_nadd + w_r;
        wbase[ntp] = wrow * 128;
        wxor[ntp]  = wrow & 7;
    }

    if (tid == 0) s_next = atomicAdd(&g_tile_ctr, 1u);
    __syncthreads();
    unsigned t = s_next;
    if (t >= NTILES) return;
    ensure_band(pre4, pim4, (int)(t >> 3), tid, &s_cvt);
    {
        const int bb = (int)(t >> 3) * BM;
        const int bk = (int)(t & 7) * BN;
        prologue_tile(sbase, bb, bk, tid);
    }

    for (;;) {
        const int block_b = (int)(t >> 3) * BM;
        const int block_k = (int)(t & 7) * BN;

        __syncthreads();
        if (tid == 0) s_next = atomicAdd(&g_tile_ctr, 1u);

        float dre[2][4][4], dim_[2][4][4];
#pragma unroll
        for (int mt = 0; mt < 2; ++mt)
#pragma unroll
            for (int nt = 0; nt < 4; ++nt)
#pragma unroll
                for (int q = 0; q < 4; ++q) { dre[mt][nt][q] = 0.f; dim_[mt][nt][q] = 0.f; }

        // -------- mainloop: 16 BK=64 slices (proven structure) --------
        for (int s = 0; s < NS; ++s) {
            asm volatile("cp.async.wait_group 1;" ::: "memory");
            __syncthreads();

            const int ls = s + PIPE - 1;
            if (ls < NS)
                load_stage(sbase, ls % PIPE, ls * BK, block_b, block_k, tid);
            asm volatile("cp.async.commit_group;" ::: "memory");

            const uint32_t sb = sbase + (uint32_t)(s % PIPE) * STAGE_BYTES;

#pragma unroll
            for (int ks = 0; ks < 4; ++ks) {
                uint32_t ar[2][4], ai[2][4], bw[2][4];
#pragma unroll
                for (int mt = 0; mt < 2; ++mt) {
                    const uint32_t ao = (uint32_t)(abase[mt] +
                                        (((2 * ks + a_chi) ^ axor[mt]) * 16));
                    ldsm4(ar[mt], sb + OFF_ARE + ao);
                    ldsm4(ai[mt], sb + OFF_AIM + ao);
                }
#pragma unroll
                for (int ntp = 0; ntp < 2; ++ntp) {
                    const uint32_t wo = (uint32_t)(wbase[ntp] +
                                        (((2 * ks + w_kc) ^ wxor[ntp]) * 16));
                    ldsm4(bw[ntp], sb + OFF_W + wo);
                }
#pragma unroll
                for (int mt = 0; mt < 2; ++mt)
#pragma unroll
                    for (int nt = 0; nt < 4; ++nt) {
                        mma16(dre[mt][nt],  ar[mt], &bw[nt >> 1][(nt & 1) * 2]);
                        mma16(dim_[mt][nt], ai[mt], &bw[nt >> 1][(nt & 1) * 2]);
                    }
            }
        }

        __syncthreads();
        const unsigned tn = s_next;

        // next tile's band-ensure + prologue overlaps this tile's epilogue
        if (tn < NTILES) {
            ensure_band(pre4, pim4, (int)(tn >> 3), tid, &s_cvt);
            const int bb = (int)(tn >> 3) * BM;
            const int bk = (int)(tn & 7) * BN;
            prologue_tile(sbase, bb, bk, tid);
        }

        // -------- epilogue: fp16 psi reads (L2-warm), folded W_INV --------
#pragma unroll
        for (int mt = 0; mt < 2; ++mt) {
#pragma unroll
            for (int rr = 0; rr < 2; ++rr) {
                const int row = block_b + warp_m * 32 + mt * 16 + g + rr * 8;
                const size_t brow = (size_t)row * KDIM;
#pragma unroll
                for (int nt = 0; nt < 4; ++nt) {
                    const int k = block_k + warp_n * 32 + nt * 8 + 2 * tg;
                    const __half2 hr = *(const __half2*)&g_pre16[brow + k];
                    const __half2 hi = *(const __half2*)&g_pim16[brow + k];
                    const float2 xr = __half22float2(hr);
                    const float2 xi = __half22float2(hi);
                    const float2 bv = *(const float2*)&bias[k];
                    const float t0 = fmaf(xr.x, dre[mt][nt][rr * 2 + 0],
                                          xi.x * dim_[mt][nt][rr * 2 + 0]);
                    const float t1 = fmaf(xr.y, dre[mt][nt][rr * 2 + 1],
                                          xi.y * dim_[mt][nt][rr * 2 + 1]);
                    float2 o;
                    o.x = sigf(fmaf(t0, W_INV, bv.x));
                    o.y = sigf(fmaf(t1, W_INV, bv.y));
                    *(float2*)&out[brow + k] = o;
                }
            }
        }

        if (tn >= NTILES) break;
        t = tn;
    }
}

extern "C" void kernel_launch(void* const* d_in, const int* in_sizes, int n_in,
                              void* d_out, int out_size)
{
    const float* pre  = (const float*)d_in[0];
    const float* pim  = (const float*)d_in[1];
    const float* Wm   = (const float*)d_in[2];
    const float* bias = (const float*)d_in[3];
    float* out = (float*)d_out;

    reset_cvtW_kernel<<<GRID_PERSIST, 256>>>((const float4*)Wm);

    cudaFuncSetAttribute(coherence_gate_h,
                         cudaFuncAttributeMaxDynamicSharedMemorySize, SMEM_BYTES);
    coherence_gate_h<<<GRID_PERSIST, NTHREADS, SMEM_BYTES>>>(pre, pim, bias, out);
}

// round 15
// speedup vs baseline: 1.0339x; 1.0339x over previous
#include <cuda_runtime.h>
#include <cuda_fp16.h>
#include <cstdint>

// CoherenceGate via fp16 mma.sync.m16n8k16 (sm_100 baseline ISA).
// out = sigmoid( psi_re*(psi_re@W^T) + psi_im*(psi_im@W^T) + bias )
// B=8192, K=1024.
//
// R15: final recombination of measured-best halves.
//  - GEMM: R13 (fp16-psi epilogue, folded W_INV; best GEMM 106.2us)
//  - Converts: R12 single-wave partitioned kernel (best convert ~11.8us)
//  - NEW: out stores via st.global.cs (evict-first) to protect L2 residency
//    of psi16/W16, which the GEMM re-reads ~8x.

#define KDIM 1024
#define BDIM 8192
#define BM 64
#define BN 128
#define BK 64
#define NTHREADS 256
#define PIPE 3
#define NS (KDIM / BK)      // 16
#define NTILES ((BDIM / BM) * (KDIM / BN))   // 1024
#define GRID_PERSIST 296

#define W_SCALE 256.0f
#define W_INV   (1.0f / 256.0f)

#define OFF_ARE 0
#define OFF_AIM 8192
#define OFF_W   16384
#define STAGE_BYTES 32768
#define SMEM_BYTES (PIPE * STAGE_BYTES)   // 98304 per CTA

// convert kernel partition: single co-resident wave
#define CVT_BLKS_RE 528
#define CVT_BLKS_IM 528
#define CVT_BLKS_W  80
#define CVT_BLKS (CVT_BLKS_RE + CVT_BLKS_IM + CVT_BLKS_W)   // 1136

__device__ __half g_pre16[(size_t)BDIM * KDIM];
__device__ __half g_pim16[(size_t)BDIM * KDIM];
__device__ __half g_W16[(size_t)KDIM * KDIM];
__device__ unsigned g_tile_ctr;

__device__ __forceinline__ uint32_t smem_u32(const void* p) {
    uint32_t a;
    asm("{ .reg .u64 t; cvta.to.shared.u64 t, %1; cvt.u32.u64 %0, t; }" : "=r"(a) : "l"(p));
    return a;
}
__device__ __forceinline__ void cp16(uint32_t dst, const void* src) {
    asm volatile("cp.async.cg.shared.global [%0], [%1], 16;" :: "r"(dst), "l"(src) : "memory");
}
__device__ __forceinline__ void ldsm4(uint32_t* r, uint32_t addr) {
    asm volatile("ldmatrix.sync.aligned.m8n8.x4.shared.b16 {%0,%1,%2,%3}, [%4];"
                 : "=r"(r[0]), "=r"(r[1]), "=r"(r[2]), "=r"(r[3]) : "r"(addr));
}
__device__ __forceinline__ void mma16(float* d, const uint32_t* a, const uint32_t* b) {
    asm volatile(
        "mma.sync.aligned.m16n8k16.row.col.f32.f16.f16.f32 "
        "{%0,%1,%2,%3},{%4,%5,%6,%7},{%8,%9},{%0,%1,%2,%3};"
        : "+f"(d[0]), "+f"(d[1]), "+f"(d[2]), "+f"(d[3])
        : "r"(a[0]), "r"(a[1]), "r"(a[2]), "r"(a[3]), "r"(b[0]), "r"(b[1]));
}
__device__ __forceinline__ float sigf(float x) {
    float t;
    asm("tanh.approx.f32 %0, %1;" : "=f"(t) : "f"(0.5f * x));
    return fmaf(0.5f, t, 0.5f);
}
// streaming (evict-first) float2 store: out is write-once, never re-read
__device__ __forceinline__ void stg_cs_f2(float* p, float2 v) {
    asm volatile("st.global.cs.v2.f32 [%0], {%1, %2};" :: "l"(p), "f"(v.x), "f"(v.y) : "memory");
}

// ---------------- phase 1: single partitioned convert kernel ----------------
__device__ __forceinline__ void cvt_range(const float4* __restrict__ src, uint2* __restrict__ dst,
                                          int n4, int nblk, int blk, float scale)
{
    const int stride = nblk * 256;
    for (int i = blk * 256 + threadIdx.x; i < n4; i += stride) {
        const float4 v = src[i];
        const __half2 h0 = __floats2half2_rn(v.x * scale, v.y * scale);
        const __half2 h1 = __floats2half2_rn(v.z * scale, v.w * scale);
        uint2 o;
        o.x = *(const uint32_t*)&h0;
        o.y = *(const uint32_t*)&h1;
        dst[i] = o;
    }
}

__global__ void cvt_all_kernel(const float4* __restrict__ pre,
                               const float4* __restrict__ pim,
                               const float4* __restrict__ Wm)
{
    if (blockIdx.x == 0 && threadIdx.x == 0) g_tile_ctr = 0u;

    const int N_PSI4 = (BDIM * KDIM) / 4;
    const int N_W4   = (KDIM * KDIM) / 4;
    const int b = blockIdx.x;

    if (b < CVT_BLKS_RE) {
        cvt_range(pre, (uint2*)g_pre16, N_PSI4, CVT_BLKS_RE, b, 1.0f);
    } else if (b < CVT_BLKS_RE + CVT_BLKS_IM) {
        cvt_range(pim, (uint2*)g_pim16, N_PSI4, CVT_BLKS_IM, b - CVT_BLKS_RE, 1.0f);
    } else {
        cvt_range(Wm, (uint2*)g_W16, N_W4, CVT_BLKS_W, b - CVT_BLKS_RE - CVT_BLKS_IM, W_SCALE);
    }
}

// ---------------- stage loader (8 cp.async / thread) ----------------
__device__ __forceinline__ void load_stage(uint32_t sbase, int buf, int j0,
                                           int block_b, int block_k, int tid)
{
    const uint32_t sb = sbase + (uint32_t)buf * STAGE_BYTES;
#pragma unroll
    for (int t = 0; t < 2; ++t) {
        const int idx = tid + t * 256;
        const int row = idx >> 3;
        const int ch  = idx & 7;
        const uint32_t so = (uint32_t)(row * 128 + ((ch ^ (row & 7)) * 16));
        const size_t ga = (size_t)(block_b + row) * KDIM + j0 + ch * 8;
        cp16(sb + OFF_ARE + so, g_pre16 + ga);
        cp16(sb + OFF_AIM + so, g_pim16 + ga);
    }
#pragma unroll
    for (int t = 0; t < 4; ++t) {
        const int idx = tid + t * 256;
        const int row = idx >> 3;
        const int ch  = idx & 7;
        const uint32_t so = (uint32_t)(row * 128 + ((ch ^ (row & 7)) * 16));
        cp16(sb + OFF_W + so, g_W16 + (size_t)(block_k + row) * KDIM + j0 + ch * 8);
    }
}

__device__ __forceinline__ void prologue_tile(uint32_t sbase, int block_b, int block_k, int tid)
{
    load_stage(sbase, 0, 0, block_b, block_k, tid);
    asm volatile("cp.async.commit_group;" ::: "memory");
    load_stage(sbase, 1, BK, block_b, block_k, tid);
    asm volatile("cp.async.commit_group;" ::: "memory");
}

// ---------------- phase 2: persistent dual-GEMM + fused sigmoid ----------------
__global__ __launch_bounds__(NTHREADS, 2)
void coherence_gate_h(const float* __restrict__ bias,
                      float* __restrict__ out)
{
    extern __shared__ __align__(128) char smem[];
    const uint32_t sbase = smem_u32(smem);
    __shared__ unsigned s_next;

    const int tid    = threadIdx.x;
    const int wid    = tid >> 5;
    const int lane   = tid & 31;
    const int g      = lane >> 2;
    const int tg     = lane & 3;
    const int warp_m = wid >> 2;   // 0..1 -> 32-row band
    const int warp_n = wid & 3;    // 0..3 -> 32-col band

    const int a_rl  = lane & 15;
    const int a_chi = lane >> 4;
    const int w_M   = lane >> 3;
    const int w_r   = lane & 7;
    const int w_kc  = w_M & 1;
    const int w_nadd = (w_M >> 1) * 8;

    int abase[2], axor[2];
#pragma unroll
    for (int mt = 0; mt < 2; ++mt) {
        const int arow = warp_m * 32 + mt * 16 + a_rl;
        abase[mt] = arow * 128;
        axor[mt]  = arow & 7;
    }
    int wbase[2], wxor[2];
#pragma unroll
    for (int ntp = 0; ntp < 2; ++ntp) {
        const int wrow = warp_n * 32 + ntp * 16 + w_nadd + w_r;
        wbase[ntp] = wrow * 128;
        wxor[ntp]  = wrow & 7;
    }

    if (tid == 0) s_next = atomicAdd(&g_tile_ctr, 1u);
    __syncthreads();
    unsigned t = s_next;
    if (t >= NTILES) return;
    {
        const int bb = (int)(t >> 3) * BM;
        const int bk = (int)(t & 7) * BN;
        prologue_tile(sbase, bb, bk, tid);
    }

    for (;;) {
        const int block_b = (int)(t >> 3) * BM;
        const int block_k = (int)(t & 7) * BN;

        __syncthreads();
        if (tid == 0) s_next = atomicAdd(&g_tile_ctr, 1u);

        float dre[2][4][4], dim_[2][4][4];
#pragma unroll
        for (int mt = 0; mt < 2; ++mt)
#pragma unroll
            for (int nt = 0; nt < 4; ++nt)
#pragma unroll
                for (int q = 0; q < 4; ++q) { dre[mt][nt][q] = 0.f; dim_[mt][nt][q] = 0.f; }

        // -------- mainloop: 16 BK=64 slices (proven structure) --------
        for (int s = 0; s < NS; ++s) {
            asm volatile("cp.async.wait_group 1;" ::: "memory");
            __syncthreads();

            const int ls = s + PIPE - 1;
            if (ls < NS)
                load_stage(sbase, ls % PIPE, ls * BK, block_b, block_k, tid);
            asm volatile("cp.async.commit_group;" ::: "memory");

            const uint32_t sb = sbase + (uint32_t)(s % PIPE) * STAGE_BYTES;

#pragma unroll
            for (int ks = 0; ks < 4; ++ks) {
                uint32_t ar[2][4], ai[2][4], bw[2][4];
#pragma unroll
                for (int mt = 0; mt < 2; ++mt) {
                    const uint32_t ao = (uint32_t)(abase[mt] +
                                        (((2 * ks + a_chi) ^ axor[mt]) * 16));
                    ldsm4(ar[mt], sb + OFF_ARE + ao);
                    ldsm4(ai[mt], sb + OFF_AIM + ao);
                }
#pragma unroll
                for (int ntp = 0; ntp < 2; ++ntp) {
                    const uint32_t wo = (uint32_t)(wbase[ntp] +
                                        (((2 * ks + w_kc) ^ wxor[ntp]) * 16));
                    ldsm4(bw[ntp], sb + OFF_W + wo);
                }
#pragma unroll
                for (int mt = 0; mt < 2; ++mt)
#pragma unroll
                    for (int nt = 0; nt < 4; ++nt) {
                        mma16(dre[mt][nt],  ar[mt], &bw[nt >> 1][(nt & 1) * 2]);
                        mma16(dim_[mt][nt], ai[mt], &bw[nt >> 1][(nt & 1) * 2]);
                    }
            }
        }

        __syncthreads();
        const unsigned tn = s_next;

        // next tile's prologue overlaps this tile's epilogue
        if (tn < NTILES) {
            const int bb = (int)(tn >> 3) * BM;
            const int bk = (int)(tn & 7) * BN;
            prologue_tile(sbase, bb, bk, tid);
        }

        // -------- epilogue: fp16 psi reads (L2-warm), folded W_INV,
        //          streaming out stores (protect L2 residency) --------
#pragma unroll
        for (int mt = 0; mt < 2; ++mt) {
#pragma unroll
            for (int rr = 0; rr < 2; ++rr) {
                const int row = block_b + warp_m * 32 + mt * 16 + g + rr * 8;
                const size_t brow = (size_t)row * KDIM;
#pragma unroll
                for (int nt = 0; nt < 4; ++nt) {
                    const int k = block_k + warp_n * 32 + nt * 8 + 2 * tg;
                    const __half2 hr = *(const __half2*)&g_pre16[brow + k];
                    const __half2 hi = *(const __half2*)&g_pim16[brow + k];
                    const float2 xr = __half22float2(hr);
                    const float2 xi = __half22float2(hi);
                    const float2 bv = *(const float2*)&bias[k];
                    const float t0 = fmaf(xr.x, dre[mt][nt][rr * 2 + 0],
                                          xi.x * dim_[mt][nt][rr * 2 + 0]);
                    const float t1 = fmaf(xr.y, dre[mt][nt][rr * 2 + 1],
                                          xi.y * dim_[mt][nt][rr * 2 + 1]);
                    float2 o;
                    o.x = sigf(fmaf(t0, W_INV, bv.x));
                    o.y = sigf(fmaf(t1, W_INV, bv.y));
                    stg_cs_f2(&out[brow + k], o);
                }
            }
        }

        if (tn >= NTILES) break;
        t = tn;
    }
}

extern "C" void kernel_launch(void* const* d_in, const int* in_sizes, int n_in,
                              void* d_out, int out_size)
{
    const float* pre  = (const float*)d_in[0];
    const float* pim  = (const float*)d_in[1];
    const float* Wm   = (const float*)d_in[2];
    const float* bias = (const float*)d_in[3];
    float* out = (float*)d_out;

    cvt_all_kernel<<<CVT_BLKS, 256>>>((const float4*)pre, (const float4*)pim,
                                      (const float4*)Wm);

    cudaFuncSetAttribute(coherence_gate_h,
                         cudaFuncAttributeMaxDynamicSharedMemorySize, SMEM_BYTES);
    coherence_gate_h<<<GRID_PERSIST, NTHREADS, SMEM_BYTES>>>(bias, out);
}

// round 16
// speedup vs baseline: 1.0483x; 1.0140x over previous
#include <cuda_runtime.h>
#include <cuda_fp16.h>
#include <cstdint>

// CoherenceGate via fp16 mma.sync.m16n8k16 (sm_100 baseline ISA).
// out = sigmoid( psi_re*(psi_re@W^T) + psi_im*(psi_im@W^T) + bias )
// B=8192, K=1024.
//
// R16: R12 config (twice-measured best total 118.8us: fp32-psi epilogue,
//      single-wave convert kernel) + two strict micro-improvements:
//      folded W_INV in the logit FMA, and st.global.cs for out stores.

#define KDIM 1024
#define BDIM 8192
#define BM 64
#define BN 128
#define BK 64
#define NTHREADS 256
#define PIPE 3
#define NS (KDIM / BK)      // 16
#define NTILES ((BDIM / BM) * (KDIM / BN))   // 1024
#define GRID_PERSIST 296

#define W_SCALE 256.0f
#define W_INV   (1.0f / 256.0f)

#define OFF_ARE 0
#define OFF_AIM 8192
#define OFF_W   16384
#define STAGE_BYTES 32768
#define SMEM_BYTES (PIPE * STAGE_BYTES)   // 98304 per CTA

// convert kernel partition: single co-resident wave
#define CVT_BLKS_RE 528
#define CVT_BLKS_IM 528
#define CVT_BLKS_W  80
#define CVT_BLKS (CVT_BLKS_RE + CVT_BLKS_IM + CVT_BLKS_W)   // 1136

__device__ __half g_pre16[(size_t)BDIM * KDIM];
__device__ __half g_pim16[(size_t)BDIM * KDIM];
__device__ __half g_W16[(size_t)KDIM * KDIM];
__device__ unsigned g_tile_ctr;

__device__ __forceinline__ uint32_t smem_u32(const void* p) {
    uint32_t a;
    asm("{ .reg .u64 t; cvta.to.shared.u64 t, %1; cvt.u32.u64 %0, t; }" : "=r"(a) : "l"(p));
    return a;
}
__device__ __forceinline__ void cp16(uint32_t dst, const void* src) {
    asm volatile("cp.async.cg.shared.global [%0], [%1], 16;" :: "r"(dst), "l"(src) : "memory");
}
__device__ __forceinline__ void ldsm4(uint32_t* r, uint32_t addr) {
    asm volatile("ldmatrix.sync.aligned.m8n8.x4.shared.b16 {%0,%1,%2,%3}, [%4];"
                 : "=r"(r[0]), "=r"(r[1]), "=r"(r[2]), "=r"(r[3]) : "r"(addr));
}
__device__ __forceinline__ void mma16(float* d, const uint32_t* a, const uint32_t* b) {
    asm volatile(
        "mma.sync.aligned.m16n8k16.row.col.f32.f16.f16.f32 "
        "{%0,%1,%2,%3},{%4,%5,%6,%7},{%8,%9},{%0,%1,%2,%3};"
        : "+f"(d[0]), "+f"(d[1]), "+f"(d[2]), "+f"(d[3])
        : "r"(a[0]), "r"(a[1]), "r"(a[2]), "r"(a[3]), "r"(b[0]), "r"(b[1]));
}
__device__ __forceinline__ float sigf(float x) {
    float t;
    asm("tanh.approx.f32 %0, %1;" : "=f"(t) : "f"(0.5f * x));
    return fmaf(0.5f, t, 0.5f);
}
// streaming (evict-first) float2 store: out is write-once, never re-read
__device__ __forceinline__ void stg_cs_f2(float* p, float2 v) {
    asm volatile("st.global.cs.v2.f32 [%0], {%1, %2};" :: "l"(p), "f"(v.x), "f"(v.y) : "memory");
}

// ---------------- phase 1: single partitioned convert kernel ----------------
__device__ __forceinline__ void cvt_range(const float4* __restrict__ src, uint2* __restrict__ dst,
                                          int n4, int nblk, int blk, float scale)
{
    const int stride = nblk * 256;
    for (int i = blk * 256 + threadIdx.x; i < n4; i += stride) {
        const float4 v = src[i];
        const __half2 h0 = __floats2half2_rn(v.x * scale, v.y * scale);
        const __half2 h1 = __floats2half2_rn(v.z * scale, v.w * scale);
        uint2 o;
        o.x = *(const uint32_t*)&h0;
        o.y = *(const uint32_t*)&h1;
        dst[i] = o;
    }
}

__global__ void cvt_all_kernel(const float4* __restrict__ pre,
                               const float4* __restrict__ pim,
                               const float4* __restrict__ Wm)
{
    if (blockIdx.x == 0 && threadIdx.x == 0) g_tile_ctr = 0u;

    const int N_PSI4 = (BDIM * KDIM) / 4;
    const int N_W4   = (KDIM * KDIM) / 4;
    const int b = blockIdx.x;

    if (b < CVT_BLKS_RE) {
        cvt_range(pre, (uint2*)g_pre16, N_PSI4, CVT_BLKS_RE, b, 1.0f);
    } else if (b < CVT_BLKS_RE + CVT_BLKS_IM) {
        cvt_range(pim, (uint2*)g_pim16, N_PSI4, CVT_BLKS_IM, b - CVT_BLKS_RE, 1.0f);
    } else {
        cvt_range(Wm, (uint2*)g_W16, N_W4, CVT_BLKS_W, b - CVT_BLKS_RE - CVT_BLKS_IM, W_SCALE);
    }
}

// ---------------- stage loader (8 cp.async / thread) ----------------
__device__ __forceinline__ void load_stage(uint32_t sbase, int buf, int j0,
                                           int block_b, int block_k, int tid)
{
    const uint32_t sb = sbase + (uint32_t)buf * STAGE_BYTES;
#pragma unroll
    for (int t = 0; t < 2; ++t) {
        const int idx = tid + t * 256;
        const int row = idx >> 3;
        const int ch  = idx & 7;
        const uint32_t so = (uint32_t)(row * 128 + ((ch ^ (row & 7)) * 16));
        const size_t ga = (size_t)(block_b + row) * KDIM + j0 + ch * 8;
        cp16(sb + OFF_ARE + so, g_pre16 + ga);
        cp16(sb + OFF_AIM + so, g_pim16 + ga);
    }
#pragma unroll
    for (int t = 0; t < 4; ++t) {
        const int idx = tid + t * 256;
        const int row = idx >> 3;
        const int ch  = idx & 7;
        const uint32_t so = (uint32_t)(row * 128 + ((ch ^ (row & 7)) * 16));
        cp16(sb + OFF_W + so, g_W16 + (size_t)(block_k + row) * KDIM + j0 + ch * 8);
    }
}

__device__ __forceinline__ void prologue_tile(uint32_t sbase, int block_b, int block_k, int tid)
{
    load_stage(sbase, 0, 0, block_b, block_k, tid);
    asm volatile("cp.async.commit_group;" ::: "memory");
    load_stage(sbase, 1, BK, block_b, block_k, tid);
    asm volatile("cp.async.commit_group;" ::: "memory");
}

// ---------------- phase 2: persistent dual-GEMM + fused sigmoid ----------------
__global__ __launch_bounds__(NTHREADS, 2)
void coherence_gate_h(const float* __restrict__ pre,
                      const float* __restrict__ pim,
                      const float* __restrict__ bias,
                      float* __restrict__ out)
{
    extern __shared__ __align__(128) char smem[];
    const uint32_t sbase = smem_u32(smem);
    __shared__ unsigned s_next;

    const int tid    = threadIdx.x;
    const int wid    = tid >> 5;
    const int lane   = tid & 31;
    const int g      = lane >> 2;
    const int tg     = lane & 3;
    const int warp_m = wid >> 2;   // 0..1 -> 32-row band
    const int warp_n = wid & 3;    // 0..3 -> 32-col band

    const int a_rl  = lane & 15;
    const int a_chi = lane >> 4;
    const int w_M   = lane >> 3;
    const int w_r   = lane & 7;
    const int w_kc  = w_M & 1;
    const int w_nadd = (w_M >> 1) * 8;

    int abase[2], axor[2];
#pragma unroll
    for (int mt = 0; mt < 2; ++mt) {
        const int arow = warp_m * 32 + mt * 16 + a_rl;
        abase[mt] = arow * 128;
        axor[mt]  = arow & 7;
    }
    int wbase[2], wxor[2];
#pragma unroll
    for (int ntp = 0; ntp < 2; ++ntp) {
        const int wrow = warp_n * 32 + ntp * 16 + w_nadd + w_r;
        wbase[ntp] = wrow * 128;
        wxor[ntp]  = wrow & 7;
    }

    if (tid == 0) s_next = atomicAdd(&g_tile_ctr, 1u);
    __syncthreads();
    unsigned t = s_next;
    if (t >= NTILES) return;
    {
        const int bb = (int)(t >> 3) * BM;
        const int bk = (int)(t & 7) * BN;
        prologue_tile(sbase, bb, bk, tid);
    }

    for (;;) {
        const int block_b = (int)(t >> 3) * BM;
        const int block_k = (int)(t & 7) * BN;

        __syncthreads();
        if (tid == 0) s_next = atomicAdd(&g_tile_ctr, 1u);

        float dre[2][4][4], dim_[2][4][4];
#pragma unroll
        for (int mt = 0; mt < 2; ++mt)
#pragma unroll
            for (int nt = 0; nt < 4; ++nt)
#pragma unroll
                for (int q = 0; q < 4; ++q) { dre[mt][nt][q] = 0.f; dim_[mt][nt][q] = 0.f; }

        // -------- mainloop: 16 BK=64 slices (R12-proven structure) --------
        for (int s = 0; s < NS; ++s) {
            asm volatile("cp.async.wait_group 1;" ::: "memory");
            __syncthreads();

            const int ls = s + PIPE - 1;
            if (ls < NS)
                load_stage(sbase, ls % PIPE, ls * BK, block_b, block_k, tid);
            asm volatile("cp.async.commit_group;" ::: "memory");

            const uint32_t sb = sbase + (uint32_t)(s % PIPE) * STAGE_BYTES;

#pragma unroll
            for (int ks = 0; ks < 4; ++ks) {
                uint32_t ar[2][4], ai[2][4], bw[2][4];
#pragma unroll
                for (int mt = 0; mt < 2; ++mt) {
                    const uint32_t ao = (uint32_t)(abase[mt] +
                                        (((2 * ks + a_chi) ^ axor[mt]) * 16));
                    ldsm4(ar[mt], sb + OFF_ARE + ao);
                    ldsm4(ai[mt], sb + OFF_AIM + ao);
                }
#pragma unroll
                for (int ntp = 0; ntp < 2; ++ntp) {
                    const uint32_t wo = (uint32_t)(wbase[ntp] +
                                        (((2 * ks + w_kc) ^ wxor[ntp]) * 16));
                    ldsm4(bw[ntp], sb + OFF_W + wo);
                }
#pragma unroll
                for (int mt = 0; mt < 2; ++mt)
#pragma unroll
                    for (int nt = 0; nt < 4; ++nt) {
                        mma16(dre[mt][nt],  ar[mt], &bw[nt >> 1][(nt & 1) * 2]);
                        mma16(dim_[mt][nt], ai[mt], &bw[nt >> 1][(nt & 1) * 2]);
                    }
            }
        }

        __syncthreads();
        const unsigned tn = s_next;

        // next tile's prologue overlaps this tile's epilogue
        if (tn < NTILES) {
            const int bb = (int)(tn >> 3) * BM;
            const int bk = (int)(tn & 7) * BN;
            prologue_tile(sbase, bb, bk, tid);
        }

        // -------- epilogue: fp32 psi reads, folded W_INV, streaming stores ----
#pragma unroll
        for (int mt = 0; mt < 2; ++mt) {
#pragma unroll
            for (int rr = 0; rr < 2; ++rr) {
                const int row = block_b + warp_m * 32 + mt * 16 + g + rr * 8;
                const size_t brow = (size_t)row * KDIM;
#pragma unroll
                for (int nt = 0; nt < 4; ++nt) {
                    const int k = block_k + warp_n * 32 + nt * 8 + 2 * tg;
                    const float2 xr = *(const float2*)&pre[brow + k];
                    const float2 xi = *(const float2*)&pim[brow + k];
                    const float2 bv = *(const float2*)&bias[k];
                    // logit = (xr*ur_s + xi*ui_s) * W_INV + bias
                    const float t0 = fmaf(xr.x, dre[mt][nt][rr * 2 + 0],
                                          xi.x * dim_[mt][nt][rr * 2 + 0]);
                    const float t1 = fmaf(xr.y, dre[mt][nt][rr * 2 + 1],
                                          xi.y * dim_[mt][nt][rr * 2 + 1]);
                    float2 o;
                    o.x = sigf(fmaf(t0, W_INV, bv.x));
                    o.y = sigf(fmaf(t1, W_INV, bv.y));
                    stg_cs_f2(&out[brow + k], o);
                }
            }
        }

        if (tn >= NTILES) break;
        t = tn;
    }
}

extern "C" void kernel_launch(void* const* d_in, const int* in_sizes, int n_in,
                              void* d_out, int out_size)
{
    const float* pre  = (const float*)d_in[0];
    const float* pim  = (const float*)d_in[1];
    const float* Wm   = (const float*)d_in[2];
    const float* bias = (const float*)d_in[3];
    float* out = (float*)d_out;

    cvt_all_kernel<<<CVT_BLKS, 256>>>((const float4*)pre, (const float4*)pim,
                                      (const float4*)Wm);

    cudaFuncSetAttribute(coherence_gate_h,
                         cudaFuncAttributeMaxDynamicSharedMemorySize, SMEM_BYTES);
    coherence_gate_h<<<GRID_PERSIST, NTHREADS, SMEM_BYTES>>>(pre, pim, bias, out);
}